// round 1
// baseline (speedup 1.0000x reference)
#include <cuda_runtime.h>
#include <math.h>

#define BATCH 64
#define ONUM  32
#define INUM  512
#define DD    64
#define OD    (ONUM * DD)        // 2048
#define IB    16                 // i's per GEMM CTA

// ---------------- scratch (device globals; no allocation allowed) ------------
__device__ float g_xhat[(size_t)BATCH * INUM * ONUM * DD]; // [b][i][o][d] 268MB
__device__ float g_s[3][BATCH * OD];                        // s0, s1, s2
__device__ float g_out0[BATCH * OD];
__device__ float g_out1[BATCH * OD];
__device__ float g_b1[(size_t)BATCH * INUM * ONUM];         // [b][i][o]

// ---------------- zero the atomic accumulators -------------------------------
__global__ void zero_s_kernel() {
    int idx = blockIdx.x * blockDim.x + threadIdx.x;
    if (idx < 3 * BATCH * OD) (&g_s[0][0])[idx] = 0.0f;
}

// ---------------- x_hat GEMM + fused s0 accumulation -------------------------
// grid (INUM/IB, ONUM), block 256.
// C[b][d] = sum_m x[b][i][m] * W[o][i][d][m], per (o,i). 64x64x64.
__global__ __launch_bounds__(256) void gemm_xhat_kernel(
    const float* __restrict__ x, const float* __restrict__ w)
{
    __shared__ float xT[64 * 68];  // [m][b], padded stride 68
    __shared__ float wT[64 * 68];  // [m][d]

    const int tid = threadIdx.x;
    const int o  = blockIdx.y;
    const int i0 = blockIdx.x * IB;
    const int ty = tid >> 4;        // 0..15 -> b block
    const int tx = tid & 15;        // 0..15 -> d block
    const int rb = ty * 4;
    const int cd = tx * 4;

    float s0acc[16];
#pragma unroll
    for (int k = 0; k < 16; k++) s0acc[k] = 0.0f;

    for (int ii = 0; ii < IB; ii++) {
        const int i = i0 + ii;
        // cooperative transpose-load: x[:,i,:] -> xT[m][b], W[o][i] -> wT[m][d]
#pragma unroll
        for (int r = 0; r < 4; r++) {
            int idx = tid + r * 256;        // 0..1023
            int row = idx >> 4;             // b (or d)
            int f4  = idx & 15;             // which float4 along m
            float4 vx = *(const float4*)(x + ((size_t)row * INUM + i) * 64 + f4 * 4);
            float4 vw = *(const float4*)(w + (((size_t)o * INUM + i) * 64 + row) * 64 + f4 * 4);
            int m0 = f4 * 4;
            xT[(m0 + 0) * 68 + row] = vx.x;
            xT[(m0 + 1) * 68 + row] = vx.y;
            xT[(m0 + 2) * 68 + row] = vx.z;
            xT[(m0 + 3) * 68 + row] = vx.w;
            wT[(m0 + 0) * 68 + row] = vw.x;
            wT[(m0 + 1) * 68 + row] = vw.y;
            wT[(m0 + 2) * 68 + row] = vw.z;
            wT[(m0 + 3) * 68 + row] = vw.w;
        }
        __syncthreads();

        float acc[16];
#pragma unroll
        for (int k = 0; k < 16; k++) acc[k] = 0.0f;

#pragma unroll 8
        for (int m = 0; m < 64; m++) {
            float4 a  = *(const float4*)&xT[m * 68 + rb];
            float4 bb = *(const float4*)&wT[m * 68 + cd];
            acc[ 0] += a.x * bb.x; acc[ 1] += a.x * bb.y; acc[ 2] += a.x * bb.z; acc[ 3] += a.x * bb.w;
            acc[ 4] += a.y * bb.x; acc[ 5] += a.y * bb.y; acc[ 6] += a.y * bb.z; acc[ 7] += a.y * bb.w;
            acc[ 8] += a.z * bb.x; acc[ 9] += a.z * bb.y; acc[10] += a.z * bb.z; acc[11] += a.z * bb.w;
            acc[12] += a.w * bb.x; acc[13] += a.w * bb.y; acc[14] += a.w * bb.z; acc[15] += a.w * bb.w;
        }

        // store x_hat[b][i][o][d] and accumulate s0
#pragma unroll
        for (int jb = 0; jb < 4; jb++) {
            float4 v = make_float4(acc[jb * 4 + 0], acc[jb * 4 + 1],
                                   acc[jb * 4 + 2], acc[jb * 4 + 3]);
            *(float4*)(g_xhat + ((size_t)(rb + jb) * INUM + i) * (size_t)OD + o * DD + cd) = v;
            s0acc[jb * 4 + 0] += v.x;
            s0acc[jb * 4 + 1] += v.y;
            s0acc[jb * 4 + 2] += v.z;
            s0acc[jb * 4 + 3] += v.w;
        }
        __syncthreads();
    }

    const float sc = 1.0f / (float)ONUM;   // softmax of zeros
#pragma unroll
    for (int jb = 0; jb < 4; jb++)
#pragma unroll
        for (int jd = 0; jd < 4; jd++)
            atomicAdd(&g_s[0][(rb + jb) * OD + o * DD + cd + jd],
                      s0acc[jb * 4 + jd] * sc);
}

// ---------------- squash: v = (n2/(1+n2)) * s / (n + 1e-8) -------------------
// one warp per (b,o) row of 64
__global__ void squash_kernel(const float* __restrict__ s, float* __restrict__ v)
{
    int gw   = (blockIdx.x * blockDim.x + threadIdx.x) >> 5;
    int lane = threadIdx.x & 31;
    if (gw >= BATCH * ONUM) return;
    const float* row = s + (size_t)gw * 64;
    float a = row[lane];
    float b = row[lane + 32];
    float ss = a * a + b * b;
#pragma unroll
    for (int off = 16; off; off >>= 1) ss += __shfl_xor_sync(0xffffffffu, ss, off);
    float n = sqrtf(ss);
    float f = (ss / (1.0f + ss)) / (n + 1e-8f);
    v[(size_t)gw * 64 + lane]      = a * f;
    v[(size_t)gw * 64 + lane + 32] = b * f;
}

// ---------------- fused routing pass -----------------------------------------
// MODE 0: logits = agree(out_prev); write b1; accumulate s_next
// MODE 1: logits = b1 + agree(out_prev); accumulate s_next
// grid (BATCH, INUM/32), block 256. Each CTA: one b, 32 i's, all o.
template <int MODE>
__global__ __launch_bounds__(256) void route_pass_kernel(
    const float* __restrict__ out_prev, float* __restrict__ s_next)
{
    __shared__ float xh[OD];
    __shared__ float op[OD];
    __shared__ float sacc[OD];
    __shared__ float tarr[ONUM];
    __shared__ float carr[ONUM];

    const int tid = threadIdx.x;
    const int b   = blockIdx.x;
    const int i0  = blockIdx.y * 32;
    const int og  = tid >> 3;      // 0..31 (o index for dot stage)
    const int l8  = tid & 7;

#pragma unroll
    for (int k = 0; k < 8; k++) {
        int idx = tid + k * 256;
        op[idx]   = out_prev[(size_t)b * OD + idx];
        sacc[idx] = 0.0f;
    }
    __syncthreads();

    for (int ii = 0; ii < 32; ii++) {
        const int i = i0 + ii;
        const float* src = g_xhat + ((size_t)b * INUM + i) * (size_t)OD;
#pragma unroll
        for (int k = 0; k < 2; k++) {
            int q = tid + k * 256;
            *(float4*)&xh[q * 4] = *(const float4*)(src + q * 4);
        }
        __syncthreads();

        // agreement dot per o (8 lanes per o)
        float p = 0.0f;
#pragma unroll
        for (int k = 0; k < 8; k++) {
            int d = l8 + k * 8;
            p += xh[og * 64 + d] * op[og * 64 + d];
        }
        p += __shfl_down_sync(0xffffffffu, p, 4, 8);
        p += __shfl_down_sync(0xffffffffu, p, 2, 8);
        p += __shfl_down_sync(0xffffffffu, p, 1, 8);
        if (l8 == 0) {
            if (MODE == 1) p += g_b1[((size_t)b * INUM + i) * ONUM + og];
            else           g_b1[((size_t)b * INUM + i) * ONUM + og] = p;
            tarr[og] = p;
        }
        __syncthreads();

        // softmax over the 32 o's (warp 0)
        if (tid < 32) {
            float t = tarr[tid];
            float m = t;
#pragma unroll
            for (int off = 16; off; off >>= 1)
                m = fmaxf(m, __shfl_xor_sync(0xffffffffu, m, off));
            float e = expf(t - m);
            float s = e;
#pragma unroll
            for (int off = 16; off; off >>= 1)
                s += __shfl_xor_sync(0xffffffffu, s, off);
            carr[tid] = e / s;
        }
        __syncthreads();

        // weighted accumulate
#pragma unroll
        for (int k = 0; k < 8; k++) {
            int idx = tid + k * 256;
            sacc[idx] += carr[idx >> 6] * xh[idx];
        }
        __syncthreads();
    }

#pragma unroll
    for (int k = 0; k < 8; k++) {
        int idx = tid + k * 256;
        atomicAdd(&s_next[(size_t)b * OD + idx], sacc[idx]);
    }
}

// ---------------- launch ------------------------------------------------------
extern "C" void kernel_launch(void* const* d_in, const int* in_sizes, int n_in,
                              void* d_out, int out_size)
{
    const float* x = (const float*)d_in[0];
    const float* w = (const float*)d_in[1];
    float* out = (float*)d_out;

    float* s_base;  cudaGetSymbolAddress((void**)&s_base,  g_s);
    float* out0;    cudaGetSymbolAddress((void**)&out0,    g_out0);
    float* out1;    cudaGetSymbolAddress((void**)&out1,    g_out1);
    float* s0 = s_base;
    float* s1 = s_base + BATCH * OD;
    float* s2 = s_base + 2 * BATCH * OD;

    zero_s_kernel<<<(3 * BATCH * OD + 255) / 256, 256>>>();

    gemm_xhat_kernel<<<dim3(INUM / IB, ONUM), 256>>>(x, w);

    squash_kernel<<<(BATCH * ONUM) / 8, 256>>>(s0, out0);

    route_pass_kernel<0><<<dim3(BATCH, INUM / 32), 256>>>(out0, s1);

    squash_kernel<<<(BATCH * ONUM) / 8, 256>>>(s1, out1);

    route_pass_kernel<1><<<dim3(BATCH, INUM / 32), 256>>>(out1, s2);

    squash_kernel<<<(BATCH * ONUM) / 8, 256>>>(s2, out);
}